// round 10
// baseline (speedup 1.0000x reference)
#include <cuda_runtime.h>
#include <cstdint>

#define B_      128
#define G_      10000
#define KW_     20
#define GC_     30000
#define LAT_    2000
#define INLEN_  200000

#define KSPLIT  15
#define KCHUNK  2016          // 15*2016 >= 30000
#define ZLD     2048

#define BK      32
#define SAK     36            // padded row stride (floats)
#define TILE_F  (128 * SAK)   // floats per operand tile
#define TILE_B  (TILE_F * 4)  // 18432 bytes
#define NST     2
#define STAGE_BYTES (2 * TILE_B)          // A + W
#define SMEM_DYN    (NST * STAGE_BYTES)   // 73728 -> 2 CTAs/SM

// ----- scratch (static device globals; allocation-free rule) -----
__device__ float g_h[B_ * GC_];
__device__ float g_zpart[KSPLIT * B_ * ZLD];
__device__ float g_z[B_ * LAT_];
__device__ float g_d[B_ * GC_];

__device__ __forceinline__ float lrelu(float v) { return v >= 0.0f ? v : 0.1f * v; }

__device__ __forceinline__ uint32_t smem_u32(const void* p) {
    return (uint32_t)__cvta_generic_to_shared(p);
}
__device__ __forceinline__ void cp_async16(uint32_t dst, const void* src, int sz) {
    asm volatile("cp.async.cg.shared.global [%0], [%1], 16, %2;"
                 :: "r"(dst), "l"(src), "r"(sz));
}
#define CP_COMMIT() asm volatile("cp.async.commit_group;" ::: "memory")
#define CP_WAITN()  asm volatile("cp.async.wait_group 1;" ::: "memory")
#define CP_WAIT0()  asm volatile("cp.async.wait_group 0;" ::: "memory")

// pack float2 -> bf16x2 (round-nearest): lo = v.x, hi = v.y
__device__ __forceinline__ uint32_t bf2(float2 v) {
    uint32_t r;
    asm("cvt.rn.bf16x2.f32 %0, %1, %2;" : "=r"(r) : "f"(v.y), "f"(v.x));
    return r;
}

__device__ __forceinline__ void mma_bf16(float c[4], const uint32_t a[4],
                                         uint32_t b0, uint32_t b1) {
    asm volatile(
        "mma.sync.aligned.m16n8k16.row.col.f32.bf16.bf16.f32 "
        "{%0,%1,%2,%3}, {%4,%5,%6,%7}, {%8,%9}, {%0,%1,%2,%3};"
        : "+f"(c[0]), "+f"(c[1]), "+f"(c[2]), "+f"(c[3])
        : "r"(a[0]), "r"(a[1]), "r"(a[2]), "r"(a[3]), "r"(b0), "r"(b1));
}

// ---------------------------------------------------------------------------
// K1: encoder grouped conv
// ---------------------------------------------------------------------------
__global__ void __launch_bounds__(192)
enc_conv_kernel(const float* __restrict__ x, const float* __restrict__ ew,
                const float* __restrict__ eb) {
    __shared__ float sx[64 * KW_];
    const int b  = blockIdx.y;
    const int g0 = blockIdx.x * 64;
    const int ng = (G_ - g0 < 64) ? (G_ - g0) : 64;
    const int nval = ng * KW_;
    for (int i = threadIdx.x; i < nval; i += 192)
        sx[i] = x[(size_t)b * INLEN_ + (size_t)g0 * KW_ + i];
    __syncthreads();
    const int j  = threadIdx.x;
    const int gl = j / 3;
    const int c  = j - gl * 3;
    const int g  = g0 + gl;
    if (gl < ng) {
        const float* w  = ew + (size_t)g * 60 + c * 20;
        const float* xv = sx + gl * KW_;
        float acc = eb[g * 3 + c];
#pragma unroll
        for (int k = 0; k < KW_; k++) acc = fmaf(xv[k], w[k], acc);
        g_h[(size_t)b * GC_ + g * 3 + c] = lrelu(acc);
    }
}

// ---------------------------------------------------------------------------
// bf16 mma.sync GEMM: C[128, ntile] (+)= A[128,K] x W[N,K]^T
//   fp32 staged in SMEM via cp.async; fragments converted to bf16 in regs.
//   mode 0: A=g_h, C=g_zpart + by*B_*ZLD (raw split-K partial)
//   mode 1: A=g_z, C=g_d, epilogue lrelu(acc + bias[n])
// 256 threads, block tile 128x128x32, warp grid 2x4 (warp tile 64x32),
// 2-stage cp.async pipeline, 2 CTAs/SM.
// ---------------------------------------------------------------------------
__global__ void __launch_bounds__(256, 2)
gemm_tc(const float* __restrict__ Wg, const float* __restrict__ bias,
        int lda, int ldw, int ldc, int Ntot, int Ktot, int mode)
{
    extern __shared__ float smem[];
    const int tid  = threadIdx.x;
    const int lane = tid & 31;
    const int wid  = tid >> 5;
    const int gq   = lane >> 2;    // group id 0..7
    const int tg   = lane & 3;     // thread-in-group 0..3
    const int wm   = wid >> 2;     // 0..1  (M)
    const int wn   = wid & 3;      // 0..3  (N)

    const int n0 = blockIdx.x * 128;
    const int k0 = blockIdx.y * KCHUNK;
    const int k1 = (k0 + KCHUNK < Ktot) ? (k0 + KCHUNK) : Ktot;
    const int T  = (k1 - k0 + BK - 1) >> 5;

    const float* A = (mode == 0) ? g_h : g_z;
    float* C = (mode == 0) ? (g_zpart + (size_t)blockIdx.y * (B_ * (size_t)ZLD))
                           : g_d;

    const uint32_t sbase = smem_u32(smem);

    // loader mapping: 1024 16B-segments per operand tile; 4 per thread.
    auto load_tile = [&](int t, int s) {
        const int kb = k0 + (t << 5);
        const uint32_t sa = sbase + (uint32_t)s * STAGE_BYTES;
        const uint32_t sw = sa + TILE_B;
#pragma unroll
        for (int u = 0; u < 4; u++) {
            const int f   = tid + u * 256;
            const int row = f >> 3;
            const int seg = f & 7;
            const int kk  = kb + seg * 4;
            const int okA = (kk + 4 <= k1) ? 16 : 0;
            const uint32_t doff = (uint32_t)(row * (SAK * 4) + seg * 16);
            cp_async16(sa + doff, okA ? (A + (size_t)row * lda + kk) : A, okA);
            const int n   = n0 + row;
            const int okW = (okA && n < Ntot) ? 16 : 0;
            cp_async16(sw + doff, okW ? (Wg + (size_t)n * ldw + kk) : Wg, okW);
        }
        CP_COMMIT();
    };

    float acc[4][4][4];
#pragma unroll
    for (int i = 0; i < 4; i++)
#pragma unroll
        for (int j = 0; j < 4; j++)
#pragma unroll
            for (int r = 0; r < 4; r++) acc[i][j][r] = 0.0f;

    load_tile(0, 0);
    if (T > 1) load_tile(1, 1);

    for (int t = 0; t < T; t++) {
        const int s = t & 1;
        if (t + NST <= T) { CP_WAITN(); } else { CP_WAIT0(); }
        __syncthreads();

        const float* As = smem + (size_t)s * (STAGE_BYTES / 4);
        const float* Ws = As + TILE_F;
#pragma unroll
        for (int ks = 0; ks < 2; ks++) {
            const int kk0 = ks * 16 + 2 * tg;
            uint32_t af[4][4];
#pragma unroll
            for (int i = 0; i < 4; i++) {
                const float* ap = As + (size_t)(wm * 64 + i * 16 + gq) * SAK + kk0;
                af[i][0] = bf2(*(const float2*)(ap));
                af[i][1] = bf2(*(const float2*)(ap + 8 * SAK));
                af[i][2] = bf2(*(const float2*)(ap + 8));
                af[i][3] = bf2(*(const float2*)(ap + 8 * SAK + 8));
            }
#pragma unroll
            for (int j = 0; j < 4; j++) {
                const float* wp = Ws + (size_t)(wn * 32 + j * 8 + gq) * SAK + kk0;
                const uint32_t b0 = bf2(*(const float2*)(wp));
                const uint32_t b1 = bf2(*(const float2*)(wp + 8));
#pragma unroll
                for (int i = 0; i < 4; i++)
                    mma_bf16(acc[i][j], af[i], b0, b1);
            }
        }
        __syncthreads();
        if (t + NST < T) load_tile(t + NST, s);
    }

    // epilogue
#pragma unroll
    for (int i = 0; i < 4; i++) {
        const int row = wm * 64 + i * 16 + gq;
#pragma unroll
        for (int j = 0; j < 4; j++) {
            const int col = n0 + wn * 32 + j * 8 + 2 * tg;
            float v0 = acc[i][j][0], v1 = acc[i][j][1];
            float v2 = acc[i][j][2], v3 = acc[i][j][3];
            if (mode == 1) {
                if (col >= Ntot) continue;
                const float b0 = bias[col], b1 = bias[col + 1];
                v0 = lrelu(v0 + b0); v1 = lrelu(v1 + b1);
                v2 = lrelu(v2 + b0); v3 = lrelu(v3 + b1);
            }
            *(float2*)(C + (size_t)row * ldc + col) = make_float2(v0, v1);
            *(float2*)(C + (size_t)(row + 8) * ldc + col) = make_float2(v2, v3);
        }
    }
}

// ---------------------------------------------------------------------------
// K3: split-K reduce + bias + leaky -> g_z
// ---------------------------------------------------------------------------
__global__ void __launch_bounds__(256)
reduce_z(const float* __restrict__ bias) {
    int idx = blockIdx.x * 256 + threadIdx.x;
    if (idx >= B_ * LAT_) return;
    int b = idx / LAT_;
    int n = idx - b * LAT_;
    float s = bias[n];
#pragma unroll
    for (int sp = 0; sp < KSPLIT; sp++)
        s += g_zpart[(size_t)sp * B_ * ZLD + (size_t)b * ZLD + n];
    g_z[idx] = lrelu(s);
}

// ---------------------------------------------------------------------------
// K5: decoder grouped conv-transpose + sigmoid (float4 vectorized)
// ---------------------------------------------------------------------------
__global__ void __launch_bounds__(256)
dec_kernel(const float* __restrict__ dw, const float* __restrict__ db,
           float* __restrict__ out) {
    int idx = blockIdx.x * 256 + threadIdx.x;
    if (idx >= B_ * G_ * 5) return;
    int b = idx / (G_ * 5);
    int r = idx - b * (G_ * 5);
    int g = r / 5;
    int q = (r - g * 5) * 4;

    const float* dd = g_d + (size_t)b * GC_ + g * 3;
    const float d0 = dd[0], d1 = dd[1], d2 = dd[2];
    const float* wb = dw + (size_t)g * 60 + q;
    const float4 w0 = *(const float4*)(wb);
    const float4 w1 = *(const float4*)(wb + 20);
    const float4 w2 = *(const float4*)(wb + 40);
    const float bs = db[g];

    float4 o;
    float a;
    a = bs + d0 * w0.x + d1 * w1.x + d2 * w2.x; o.x = 1.0f / (1.0f + __expf(-a));
    a = bs + d0 * w0.y + d1 * w1.y + d2 * w2.y; o.y = 1.0f / (1.0f + __expf(-a));
    a = bs + d0 * w0.z + d1 * w1.z + d2 * w2.z; o.z = 1.0f / (1.0f + __expf(-a));
    a = bs + d0 * w0.w + d1 * w1.w + d2 * w2.w; o.w = 1.0f / (1.0f + __expf(-a));
    *(float4*)(out + (size_t)b * INLEN_ + g * 20 + q) = o;
}

// ---------------------------------------------------------------------------
extern "C" void kernel_launch(void* const* d_in, const int* in_sizes, int n_in,
                              void* d_out, int out_size) {
    const float* x        = (const float*)d_in[0];
    const float* enc_w    = (const float*)d_in[1];
    const float* enc_b    = (const float*)d_in[2];
    const float* enc_fc_w = (const float*)d_in[3];
    const float* enc_fc_b = (const float*)d_in[4];
    const float* dec_fc_w = (const float*)d_in[5];
    const float* dec_fc_b = (const float*)d_in[6];
    const float* dec_w    = (const float*)d_in[7];
    const float* dec_b    = (const float*)d_in[8];
    float* out = (float*)d_out;

    cudaFuncSetAttribute(gemm_tc, cudaFuncAttributeMaxDynamicSharedMemorySize,
                         SMEM_DYN);

    // 1) encoder grouped conv -> g_h [128, 30000]
    enc_conv_kernel<<<dim3(157, 128), 192>>>(x, enc_w, enc_b);

    // 2) enc FC bf16 mma, split-K=15 -> g_zpart  (W=[2000,30000])
    gemm_tc<<<dim3(16, KSPLIT), 256, SMEM_DYN>>>(enc_fc_w, nullptr,
                                                 GC_, GC_, ZLD, LAT_, GC_, 0);

    // 3) reduce + bias + leaky -> g_z [128, 2000]
    reduce_z<<<(B_ * LAT_ + 255) / 256, 256>>>(enc_fc_b);

    // 4) dec FC bf16 mma, fused epilogue -> g_d [128, 30000]  (W=[30000,2000])
    gemm_tc<<<dim3(235, 1), 256, SMEM_DYN>>>(dec_fc_w, dec_fc_b,
                                             LAT_, LAT_, GC_, GC_, LAT_, 1);

    // 5) decoder conv-transpose + sigmoid -> out [128, 200000]
    dec_kernel<<<(B_ * G_ * 5 + 255) / 256, 256>>>(dec_w, dec_b, out);
}

// round 11
// speedup vs baseline: 1.0993x; 1.0993x over previous
#include <cuda_runtime.h>
#include <cstdint>

#define B_      128
#define G_      10000
#define KW_     20
#define GC_     30000
#define LAT_    2000
#define INLEN_  200000

#define KSPLIT  15
#define KCHUNK  2016          // 15*2016 >= 30000
#define ZLD     2048

#define BK      32
#define SAK     36            // padded row stride (floats) -> conflict-free frags
#define TILE_F  (128 * SAK)   // floats per operand tile
#define TILE_B  (TILE_F * 4)  // 18432 bytes
#define NST     3
#define STAGE_BYTES (2 * TILE_B)          // A + W  (36864)
#define SMEM_DYN    (NST * STAGE_BYTES)   // 110592 -> still 2 CTAs/SM

// ----- scratch (static device globals; allocation-free rule) -----
__device__ float g_h[B_ * GC_];
__device__ float g_zpart[KSPLIT * B_ * ZLD];
__device__ float g_z[B_ * LAT_];
__device__ float g_d[B_ * GC_];

__device__ __forceinline__ float lrelu(float v) { return v >= 0.0f ? v : 0.1f * v; }

__device__ __forceinline__ uint32_t smem_u32(const void* p) {
    return (uint32_t)__cvta_generic_to_shared(p);
}
__device__ __forceinline__ void cp_async16(uint32_t dst, const void* src, int sz) {
    asm volatile("cp.async.cg.shared.global [%0], [%1], 16, %2;"
                 :: "r"(dst), "l"(src), "r"(sz));
}
#define CP_COMMIT() asm volatile("cp.async.commit_group;" ::: "memory")
#define CP_WAIT1()  asm volatile("cp.async.wait_group 1;" ::: "memory")
#define CP_WAIT0()  asm volatile("cp.async.wait_group 0;" ::: "memory")

// raw fp32 bits fed as tf32 operands (HW truncation; measured 4.3e-6 final err)
__device__ __forceinline__ void mma_tf32(float c[4], uint32_t a0, uint32_t a1,
                                         uint32_t a2, uint32_t a3,
                                         uint32_t b0, uint32_t b1) {
    asm volatile(
        "mma.sync.aligned.m16n8k8.row.col.f32.tf32.tf32.f32 "
        "{%0,%1,%2,%3}, {%4,%5,%6,%7}, {%8,%9}, {%0,%1,%2,%3};"
        : "+f"(c[0]), "+f"(c[1]), "+f"(c[2]), "+f"(c[3])
        : "r"(a0), "r"(a1), "r"(a2), "r"(a3), "r"(b0), "r"(b1));
}

// ---------------------------------------------------------------------------
// K1: encoder grouped conv
// ---------------------------------------------------------------------------
__global__ void __launch_bounds__(192)
enc_conv_kernel(const float* __restrict__ x, const float* __restrict__ ew,
                const float* __restrict__ eb) {
    __shared__ float sx[64 * KW_];
    const int b  = blockIdx.y;
    const int g0 = blockIdx.x * 64;
    const int ng = (G_ - g0 < 64) ? (G_ - g0) : 64;
    const int nval = ng * KW_;
    for (int i = threadIdx.x; i < nval; i += 192)
        sx[i] = x[(size_t)b * INLEN_ + (size_t)g0 * KW_ + i];
    __syncthreads();
    const int j  = threadIdx.x;
    const int gl = j / 3;
    const int c  = j - gl * 3;
    const int g  = g0 + gl;
    if (gl < ng) {
        const float* w  = ew + (size_t)g * 60 + c * 20;
        const float* xv = sx + gl * KW_;
        float acc = eb[g * 3 + c];
#pragma unroll
        for (int k = 0; k < KW_; k++) acc = fmaf(xv[k], w[k], acc);
        g_h[(size_t)b * GC_ + g * 3 + c] = lrelu(acc);
    }
}

// ---------------------------------------------------------------------------
// tf32 mma.sync GEMM: C[128, ntile] (+)= A[128,K] x W[N,K]^T
//   mode 0: A=g_h, C=g_zpart + by*B_*ZLD (raw split-K partial)
//   mode 1: A=g_z, C=g_d, epilogue lrelu(acc + bias[n])
// 256 threads, block tile 128x128x32, warp grid 2x4 (warp tile 64x32),
// 3-stage cp.async pipeline with ONE barrier per K-tile, 2 CTAs/SM.
// ---------------------------------------------------------------------------
__global__ void __launch_bounds__(256, 2)
gemm_tc(const float* __restrict__ Wg, const float* __restrict__ bias,
        int lda, int ldw, int ldc, int Ntot, int Ktot, int mode)
{
    extern __shared__ float smem[];
    const int tid  = threadIdx.x;
    const int lane = tid & 31;
    const int wid  = tid >> 5;
    const int gq   = lane >> 2;    // group id 0..7
    const int tg   = lane & 3;     // thread-in-group 0..3
    const int wm   = wid >> 2;     // 0..1  (M)
    const int wn   = wid & 3;      // 0..3  (N)

    const int n0 = blockIdx.x * 128;
    const int k0 = blockIdx.y * KCHUNK;
    const int k1 = (k0 + KCHUNK < Ktot) ? (k0 + KCHUNK) : Ktot;
    const int T  = (k1 - k0 + BK - 1) >> 5;

    const float* A = (mode == 0) ? g_h : g_z;
    float* C = (mode == 0) ? (g_zpart + (size_t)blockIdx.y * (B_ * (size_t)ZLD))
                           : g_d;

    const uint32_t sbase = smem_u32(smem);

    // loader mapping: 1024 16B-segments per operand tile; 4 per thread.
    auto load_tile = [&](int t, int s) {
        const int kb = k0 + (t << 5);
        const uint32_t sa = sbase + (uint32_t)s * STAGE_BYTES;
        const uint32_t sw = sa + TILE_B;
#pragma unroll
        for (int u = 0; u < 4; u++) {
            const int f   = tid + u * 256;
            const int row = f >> 3;
            const int seg = f & 7;
            const int kk  = kb + seg * 4;
            const int okA = (kk + 4 <= k1) ? 16 : 0;
            const uint32_t doff = (uint32_t)(row * (SAK * 4) + seg * 16);
            cp_async16(sa + doff, okA ? (A + (size_t)row * lda + kk) : A, okA);
            const int n   = n0 + row;
            const int okW = (okA && n < Ntot) ? 16 : 0;
            cp_async16(sw + doff, okW ? (Wg + (size_t)n * ldw + kk) : Wg, okW);
        }
        CP_COMMIT();
    };

    float acc[4][4][4];
#pragma unroll
    for (int i = 0; i < 4; i++)
#pragma unroll
        for (int j = 0; j < 4; j++)
#pragma unroll
            for (int r = 0; r < 4; r++) acc[i][j][r] = 0.0f;

    load_tile(0, 0);
    if (T > 1) load_tile(1, 1);

    int s = 0;          // stage of tile t
    int sl = 2;         // stage for tile t+2
    for (int t = 0; t < T; t++) {
        if (t + 1 < T) { CP_WAIT1(); } else { CP_WAIT0(); }
        __syncthreads();
        // issue next load immediately: stage sl == (t-1)%3, free after barrier
        if (t + 2 < T) load_tile(t + 2, sl);

        const float* As = smem + (size_t)s * (STAGE_BYTES / 4);
        const float* Ws = As + TILE_F;
#pragma unroll
        for (int ks = 0; ks < 4; ks++) {
            const int kk0 = ks * 8;
            uint32_t af[4][4];
#pragma unroll
            for (int i = 0; i < 4; i++) {
                const int rb = wm * 64 + i * 16;
                const float* ap = As + (size_t)(rb + gq) * SAK + kk0 + tg;
                af[i][0] = __float_as_uint(ap[0]);
                af[i][2] = __float_as_uint(ap[4]);
                af[i][1] = __float_as_uint(ap[8 * SAK]);
                af[i][3] = __float_as_uint(ap[8 * SAK + 4]);
            }
#pragma unroll
            for (int j = 0; j < 4; j++) {
                const int n = wn * 32 + j * 8 + gq;
                const float* wp = Ws + (size_t)n * SAK + kk0 + tg;
                const uint32_t b0 = __float_as_uint(wp[0]);
                const uint32_t b1 = __float_as_uint(wp[4]);
#pragma unroll
                for (int i = 0; i < 4; i++)
                    mma_tf32(acc[i][j], af[i][0], af[i][1], af[i][2], af[i][3],
                             b0, b1);
            }
        }
        s  = (s  == NST - 1) ? 0 : s + 1;
        sl = (sl == NST - 1) ? 0 : sl + 1;
    }

    // epilogue
#pragma unroll
    for (int i = 0; i < 4; i++) {
        const int row = wm * 64 + i * 16 + gq;
#pragma unroll
        for (int j = 0; j < 4; j++) {
            const int col = n0 + wn * 32 + j * 8 + 2 * tg;
            float v0 = acc[i][j][0], v1 = acc[i][j][1];
            float v2 = acc[i][j][2], v3 = acc[i][j][3];
            if (mode == 1) {
                if (col >= Ntot) continue;
                const float b0 = bias[col], b1 = bias[col + 1];
                v0 = lrelu(v0 + b0); v1 = lrelu(v1 + b1);
                v2 = lrelu(v2 + b0); v3 = lrelu(v3 + b1);
            }
            *(float2*)(C + (size_t)row * ldc + col) = make_float2(v0, v1);
            *(float2*)(C + (size_t)(row + 8) * ldc + col) = make_float2(v2, v3);
        }
    }
}

// ---------------------------------------------------------------------------
// K3: split-K reduce + bias + leaky -> g_z
// ---------------------------------------------------------------------------
__global__ void __launch_bounds__(256)
reduce_z(const float* __restrict__ bias) {
    int idx = blockIdx.x * 256 + threadIdx.x;
    if (idx >= B_ * LAT_) return;
    int b = idx / LAT_;
    int n = idx - b * LAT_;
    float s = bias[n];
#pragma unroll
    for (int sp = 0; sp < KSPLIT; sp++)
        s += g_zpart[(size_t)sp * B_ * ZLD + (size_t)b * ZLD + n];
    g_z[idx] = lrelu(s);
}

// ---------------------------------------------------------------------------
// K5: decoder grouped conv-transpose + sigmoid (float4 vectorized)
// ---------------------------------------------------------------------------
__global__ void __launch_bounds__(256)
dec_kernel(const float* __restrict__ dw, const float* __restrict__ db,
           float* __restrict__ out) {
    int idx = blockIdx.x * 256 + threadIdx.x;
    if (idx >= B_ * G_ * 5) return;
    int b = idx / (G_ * 5);
    int r = idx - b * (G_ * 5);
    int g = r / 5;
    int q = (r - g * 5) * 4;

    const float* dd = g_d + (size_t)b * GC_ + g * 3;
    const float d0 = dd[0], d1 = dd[1], d2 = dd[2];
    const float* wb = dw + (size_t)g * 60 + q;
    const float4 w0 = *(const float4*)(wb);
    const float4 w1 = *(const float4*)(wb + 20);
    const float4 w2 = *(const float4*)(wb + 40);
    const float bs = db[g];

    float4 o;
    float a;
    a = bs + d0 * w0.x + d1 * w1.x + d2 * w2.x; o.x = 1.0f / (1.0f + __expf(-a));
    a = bs + d0 * w0.y + d1 * w1.y + d2 * w2.y; o.y = 1.0f / (1.0f + __expf(-a));
    a = bs + d0 * w0.z + d1 * w1.z + d2 * w2.z; o.z = 1.0f / (1.0f + __expf(-a));
    a = bs + d0 * w0.w + d1 * w1.w + d2 * w2.w; o.w = 1.0f / (1.0f + __expf(-a));
    *(float4*)(out + (size_t)b * INLEN_ + g * 20 + q) = o;
}

// ---------------------------------------------------------------------------
extern "C" void kernel_launch(void* const* d_in, const int* in_sizes, int n_in,
                              void* d_out, int out_size) {
    const float* x        = (const float*)d_in[0];
    const float* enc_w    = (const float*)d_in[1];
    const float* enc_b    = (const float*)d_in[2];
    const float* enc_fc_w = (const float*)d_in[3];
    const float* enc_fc_b = (const float*)d_in[4];
    const float* dec_fc_w = (const float*)d_in[5];
    const float* dec_fc_b = (const float*)d_in[6];
    const float* dec_w    = (const float*)d_in[7];
    const float* dec_b    = (const float*)d_in[8];
    float* out = (float*)d_out;

    cudaFuncSetAttribute(gemm_tc, cudaFuncAttributeMaxDynamicSharedMemorySize,
                         SMEM_DYN);

    // 1) encoder grouped conv -> g_h [128, 30000]
    enc_conv_kernel<<<dim3(157, 128), 192>>>(x, enc_w, enc_b);

    // 2) enc FC tf32 mma, split-K=15 -> g_zpart  (W=[2000,30000])
    gemm_tc<<<dim3(16, KSPLIT), 256, SMEM_DYN>>>(enc_fc_w, nullptr,
                                                 GC_, GC_, ZLD, LAT_, GC_, 0);

    // 3) reduce + bias + leaky -> g_z [128, 2000]
    reduce_z<<<(B_ * LAT_ + 255) / 256, 256>>>(enc_fc_b);

    // 4) dec FC tf32 mma, fused epilogue -> g_d [128, 30000]  (W=[30000,2000])
    gemm_tc<<<dim3(235, 1), 256, SMEM_DYN>>>(dec_fc_w, dec_fc_b,
                                             LAT_, LAT_, GC_, GC_, LAT_, 1);

    // 5) decoder conv-transpose + sigmoid -> out [128, 200000]
    dec_kernel<<<(B_ * G_ * 5 + 255) / 256, 256>>>(dec_w, dec_b, out);
}